// round 8
// baseline (speedup 1.0000x reference)
#include <cuda_runtime.h>
#include <cuda_bf16.h>

#define N_NODES 50000
#define N_EDGES 800000
#define D 64

// Scratch (device globals: allocation-free; zero-initialized at module load).
// INVARIANT: g_degi is all-zero at entry of every kernel_launch call.
//   k_count builds it, k_fill drains it back to zero. No zeroing kernel needed.
__device__ float g_xw[N_NODES * D];      // xs = (x@W) * dis[row]
__device__ float g_dis[N_NODES];
__device__ int   g_degi[N_NODES];        // edge-only in-degree (drained by k_fill)
__device__ int   g_off[N_NODES + 1];     // CSR offsets (exclusive scan, +total)
__device__ int   g_srcs[N_EDGES];        // CSR src lists grouped by dst

// ---------------------------------------------------------------------------
// K1: count in-degrees. 4 edges per thread via int4.
__global__ void __launch_bounds__(256) k_count(const int* __restrict__ ei) {
    int t = blockIdx.x * 256 + threadIdx.x;
    if (t < N_EDGES / 4) {
        int4 d = __ldg(reinterpret_cast<const int4*>(ei + N_EDGES) + t);
        atomicAdd(&g_degi[d.x], 1);
        atomicAdd(&g_degi[d.y], 1);
        atomicAdd(&g_degi[d.z], 1);
        atomicAdd(&g_degi[d.w], 1);
    }
}

// K2: single-block exclusive scan g_degi -> g_off[N+1], dis = rsqrt(deg+1)
__global__ void __launch_bounds__(1024) k_scan() {
    __shared__ int sp[1024];
    const int t = threadIdx.x;
    const int CH = (N_NODES + 1023) / 1024;   // 49
    const int base = t * CH;

    int sum = 0;
    #pragma unroll 7
    for (int k = 0; k < CH; k++) {
        int i = base + k;
        if (i < N_NODES) sum += g_degi[i];
    }
    sp[t] = sum;
    __syncthreads();

    for (int ofs = 1; ofs < 1024; ofs <<= 1) {
        int v = 0;
        if (t >= ofs) v = sp[t - ofs];
        __syncthreads();
        sp[t] += v;
        __syncthreads();
    }

    int off = (t == 0) ? 0 : sp[t - 1];
    for (int k = 0; k < CH; k++) {
        int i = base + k;
        if (i < N_NODES) {
            g_off[i] = off;
            int dg = g_degi[i];
            off += dg;
            g_dis[i] = rsqrtf((float)(dg + 1));   // +1 self loop
        }
    }
    if (t == 1023) g_off[N_NODES] = sp[1023];     // total = N_EDGES
}

// K3: xs = (x @ W) * dis[row].
// 256 threads = 64 rows x 4 col-groups of 16. x tile + W in smem.
__global__ void __launch_bounds__(256) k_gemm(const float* __restrict__ x,
                                              const float* __restrict__ W) {
    __shared__ float sW[D * D];
    __shared__ float sx[64 * D];
    float4* sW4 = reinterpret_cast<float4*>(sW);
    float4* sx4 = reinterpret_cast<float4*>(sx);

    const int tid = threadIdx.x;
    const int row0 = blockIdx.x * 64;

    #pragma unroll
    for (int i = tid; i < D * D / 4; i += 256)
        sW4[i] = reinterpret_cast<const float4*>(W)[i];
    #pragma unroll
    for (int i = tid; i < 64 * D / 4; i += 256) {
        int r = i >> 4;
        int gr = row0 + r;
        sx4[i] = (gr < N_NODES)
            ? __ldg(reinterpret_cast<const float4*>(x) + (size_t)gr * 16 + (i & 15))
            : make_float4(0.f, 0.f, 0.f, 0.f);
    }
    __syncthreads();

    const int r  = tid >> 2;     // 0..63
    const int cg = tid & 3;      // 16-col group
    float4 a0 = make_float4(0.f, 0.f, 0.f, 0.f);
    float4 a1 = a0, a2 = a0, a3 = a0;

    #pragma unroll 8
    for (int k = 0; k < D; k++) {
        float xv = sx[r * D + k];
        float4 w0 = sW4[k * 16 + cg * 4 + 0];
        float4 w1 = sW4[k * 16 + cg * 4 + 1];
        float4 w2 = sW4[k * 16 + cg * 4 + 2];
        float4 w3 = sW4[k * 16 + cg * 4 + 3];
        a0.x += xv * w0.x; a0.y += xv * w0.y; a0.z += xv * w0.z; a0.w += xv * w0.w;
        a1.x += xv * w1.x; a1.y += xv * w1.y; a1.z += xv * w1.z; a1.w += xv * w1.w;
        a2.x += xv * w2.x; a2.y += xv * w2.y; a2.z += xv * w2.z; a2.w += xv * w2.w;
        a3.x += xv * w3.x; a3.y += xv * w3.y; a3.z += xv * w3.z; a3.w += xv * w3.w;
    }

    const int gr = row0 + r;
    if (gr < N_NODES) {
        float dis = g_dis[gr];
        a0.x *= dis; a0.y *= dis; a0.z *= dis; a0.w *= dis;
        a1.x *= dis; a1.y *= dis; a1.z *= dis; a1.w *= dis;
        a2.x *= dis; a2.y *= dis; a2.z *= dis; a2.w *= dis;
        a3.x *= dis; a3.y *= dis; a3.z *= dis; a3.w *= dis;
        float4* o = reinterpret_cast<float4*>(g_xw) + (size_t)gr * 16 + cg * 4;
        o[0] = a0; o[1] = a1; o[2] = a2; o[3] = a3;
    }
}

// K4: bucket-fill CSR src lists; drains g_degi back to 0 (replay invariant).
// 2 edges per thread via int2.
__global__ void __launch_bounds__(256) k_fill(const int* __restrict__ ei) {
    int t = blockIdx.x * 256 + threadIdx.x;
    if (t < N_EDGES / 2) {
        int2 s = __ldg(reinterpret_cast<const int2*>(ei) + t);
        int2 d = __ldg(reinterpret_cast<const int2*>(ei + N_EDGES) + t);
        int p0 = g_off[d.x] + atomicAdd(&g_degi[d.x], -1) - 1;
        g_srcs[p0] = s.x;
        int p1 = g_off[d.y] + atomicAdd(&g_degi[d.y], -1) - 1;
        g_srcs[p1] = s.y;
    }
}

// K5: gather. Half-warp (16 lanes) per node, one float4 column chunk per lane
// (16 x 16B = full 256B row per gather). out[i] = dis[i]*(xs[i]+sum xs[src]) + b
__global__ void __launch_bounds__(256) k_gather(const float* __restrict__ b,
                                                float* __restrict__ out) {
    int t = blockIdx.x * 256 + threadIdx.x;
    int i = t >> 4;
    if (i >= N_NODES) return;
    int lane = t & 15;

    const float4* xs4 = reinterpret_cast<const float4*>(g_xw);
    float4 acc = __ldg(&xs4[(size_t)i * 16 + lane]);      // self term xs[i]

    int j   = __ldg(&g_off[i]);
    int end = __ldg(&g_off[i + 1]);

    for (; j + 8 <= end; j += 8) {                        // MLP = 8
        int s0 = __ldg(&g_srcs[j + 0]);
        int s1 = __ldg(&g_srcs[j + 1]);
        int s2 = __ldg(&g_srcs[j + 2]);
        int s3 = __ldg(&g_srcs[j + 3]);
        int s4 = __ldg(&g_srcs[j + 4]);
        int s5 = __ldg(&g_srcs[j + 5]);
        int s6 = __ldg(&g_srcs[j + 6]);
        int s7 = __ldg(&g_srcs[j + 7]);
        float4 v0 = __ldg(&xs4[(size_t)s0 * 16 + lane]);
        float4 v1 = __ldg(&xs4[(size_t)s1 * 16 + lane]);
        float4 v2 = __ldg(&xs4[(size_t)s2 * 16 + lane]);
        float4 v3 = __ldg(&xs4[(size_t)s3 * 16 + lane]);
        float4 v4 = __ldg(&xs4[(size_t)s4 * 16 + lane]);
        float4 v5 = __ldg(&xs4[(size_t)s5 * 16 + lane]);
        float4 v6 = __ldg(&xs4[(size_t)s6 * 16 + lane]);
        float4 v7 = __ldg(&xs4[(size_t)s7 * 16 + lane]);
        acc.x += ((v0.x + v1.x) + (v2.x + v3.x)) + ((v4.x + v5.x) + (v6.x + v7.x));
        acc.y += ((v0.y + v1.y) + (v2.y + v3.y)) + ((v4.y + v5.y) + (v6.y + v7.y));
        acc.z += ((v0.z + v1.z) + (v2.z + v3.z)) + ((v4.z + v5.z) + (v6.z + v7.z));
        acc.w += ((v0.w + v1.w) + (v2.w + v3.w)) + ((v4.w + v5.w) + (v6.w + v7.w));
    }
    for (; j < end; j++) {
        int s = __ldg(&g_srcs[j]);
        float4 v = __ldg(&xs4[(size_t)s * 16 + lane]);
        acc.x += v.x; acc.y += v.y; acc.z += v.z; acc.w += v.w;
    }

    float dis = __ldg(&g_dis[i]);
    float4 bb = __ldg(reinterpret_cast<const float4*>(b) + lane);
    float4 o;
    o.x = acc.x * dis + bb.x;
    o.y = acc.y * dis + bb.y;
    o.z = acc.z * dis + bb.z;
    o.w = acc.w * dis + bb.w;
    reinterpret_cast<float4*>(out)[(size_t)i * 16 + lane] = o;
}

extern "C" void kernel_launch(void* const* d_in, const int* in_sizes, int n_in,
                              void* d_out, int out_size) {
    const float* x  = (const float*)d_in[0];
    const int*   ei = (const int*)d_in[1];     // int64 in reference, delivered as int32
    const float* W  = (const float*)d_in[2];
    const float* b  = (const float*)d_in[3];
    float* out = (float*)d_out;

    (void)in_sizes; (void)n_in; (void)out_size;

    k_count <<<(N_EDGES / 4 + 255) / 256, 256>>>(ei);
    k_scan  <<<1, 1024>>>();
    k_gemm  <<<(N_NODES + 63) / 64, 256>>>(x, W);
    k_fill  <<<(N_EDGES / 2 + 255) / 256, 256>>>(ei);
    k_gather<<<(N_NODES * 16 + 255) / 256, 256>>>(b, out);
}

// round 9
// speedup vs baseline: 1.7068x; 1.7068x over previous
#include <cuda_runtime.h>
#include <cuda_bf16.h>

#define N_NODES 50000
#define N_EDGES 800000
#define D 64

// Scratch (device globals: allocation-free; zero-initialized at module load).
// INVARIANT: g_degi is all-zero at entry of every kernel_launch call.
//   k_count builds it, k_fill drains it back to zero. No zeroing kernel needed.
__device__ float g_xw[N_NODES * D];      // xs = (x@W) * dis[row]
__device__ float g_dis[N_NODES];
__device__ int   g_degi[N_NODES];        // edge-only in-degree (drained by k_fill)
__device__ int   g_off[N_NODES + 1];     // CSR offsets (exclusive scan, +total)
__device__ int   g_srcs[N_EDGES];        // CSR src lists grouped by dst

// ---------------------------------------------------------------------------
// K1: count in-degrees. 4 edges per thread via int4.
__global__ void __launch_bounds__(256) k_count(const int* __restrict__ ei) {
    int t = blockIdx.x * 256 + threadIdx.x;
    if (t < N_EDGES / 4) {
        int4 d = __ldg(reinterpret_cast<const int4*>(ei + N_EDGES) + t);
        atomicAdd(&g_degi[d.x], 1);
        atomicAdd(&g_degi[d.y], 1);
        atomicAdd(&g_degi[d.z], 1);
        atomicAdd(&g_degi[d.w], 1);
    }
}

// K2: single-block exclusive scan g_degi -> g_off[N+1], dis = rsqrt(deg+1)
__global__ void __launch_bounds__(1024) k_scan() {
    __shared__ int sp[1024];
    const int t = threadIdx.x;
    const int CH = (N_NODES + 1023) / 1024;   // 49
    const int base = t * CH;

    int sum = 0;
    #pragma unroll 7
    for (int k = 0; k < CH; k++) {
        int i = base + k;
        if (i < N_NODES) sum += g_degi[i];
    }
    sp[t] = sum;
    __syncthreads();

    for (int ofs = 1; ofs < 1024; ofs <<= 1) {
        int v = 0;
        if (t >= ofs) v = sp[t - ofs];
        __syncthreads();
        sp[t] += v;
        __syncthreads();
    }

    int off = (t == 0) ? 0 : sp[t - 1];
    for (int k = 0; k < CH; k++) {
        int i = base + k;
        if (i < N_NODES) {
            g_off[i] = off;
            int dg = g_degi[i];
            off += dg;
            g_dis[i] = rsqrtf((float)(dg + 1));   // +1 self loop
        }
    }
    if (t == 1023) g_off[N_NODES] = sp[1023];     // total = N_EDGES
}

// K3: xs = (x @ W) * dis[row].
// 256 threads; tile = 128 rows. Thread = 2 rows x 16 cols (acc 2x16 = 32 regs).
// sx padded to stride 68 floats (17 float4): x-read bank = (8*r2+k)%32 ->
// 8 distinct banks + 4-way broadcast = conflict-free. W-read = 4 distinct
// consecutive 64B chunks per warp = conflict-free broadcast.
#define XS 68                             // padded row stride (floats), /4 = 17
__global__ void __launch_bounds__(256) k_gemm(const float* __restrict__ x,
                                              const float* __restrict__ W) {
    __shared__ float sW[D * D];
    __shared__ float sx[128 * XS];
    float4* sW4 = reinterpret_cast<float4*>(sW);
    float4* sx4 = reinterpret_cast<float4*>(sx);

    const int tid = threadIdx.x;
    const int row0 = blockIdx.x * 128;

    #pragma unroll
    for (int i = tid; i < D * D / 4; i += 256)
        sW4[i] = reinterpret_cast<const float4*>(W)[i];
    #pragma unroll
    for (int i = tid; i < 128 * 16; i += 256) {
        int r = i >> 4;
        int c = i & 15;
        int gr = row0 + r;
        sx4[r * (XS / 4) + c] = (gr < N_NODES)
            ? __ldg(reinterpret_cast<const float4*>(x) + (size_t)gr * 16 + c)
            : make_float4(0.f, 0.f, 0.f, 0.f);
    }
    __syncthreads();

    const int r2 = tid >> 2;          // 0..63  -> rows 2*r2, 2*r2+1
    const int cg = tid & 3;           // 16-col group
    const float* x0 = sx + (2 * r2 + 0) * XS;
    const float* x1 = sx + (2 * r2 + 1) * XS;

    float4 a00, a01, a02, a03, a10, a11, a12, a13;
    a00 = a01 = a02 = a03 = make_float4(0.f, 0.f, 0.f, 0.f);
    a10 = a11 = a12 = a13 = a00;

    #pragma unroll 4
    for (int k = 0; k < D; k++) {
        float4 w0 = sW4[k * 16 + cg * 4 + 0];
        float4 w1 = sW4[k * 16 + cg * 4 + 1];
        float4 w2 = sW4[k * 16 + cg * 4 + 2];
        float4 w3 = sW4[k * 16 + cg * 4 + 3];
        float xa = x0[k];
        float xb = x1[k];
        a00.x += xa * w0.x; a00.y += xa * w0.y; a00.z += xa * w0.z; a00.w += xa * w0.w;
        a01.x += xa * w1.x; a01.y += xa * w1.y; a01.z += xa * w1.z; a01.w += xa * w1.w;
        a02.x += xa * w2.x; a02.y += xa * w2.y; a02.z += xa * w2.z; a02.w += xa * w2.w;
        a03.x += xa * w3.x; a03.y += xa * w3.y; a03.z += xa * w3.z; a03.w += xa * w3.w;
        a10.x += xb * w0.x; a10.y += xb * w0.y; a10.z += xb * w0.z; a10.w += xb * w0.w;
        a11.x += xb * w1.x; a11.y += xb * w1.y; a11.z += xb * w1.z; a11.w += xb * w1.w;
        a12.x += xb * w2.x; a12.y += xb * w2.y; a12.z += xb * w2.z; a12.w += xb * w2.w;
        a13.x += xb * w3.x; a13.y += xb * w3.y; a13.z += xb * w3.z; a13.w += xb * w3.w;
    }

    const int gr0 = row0 + 2 * r2;
    if (gr0 < N_NODES) {
        float dis = g_dis[gr0];
        float4* o = reinterpret_cast<float4*>(g_xw) + (size_t)gr0 * 16 + cg * 4;
        o[0] = make_float4(a00.x * dis, a00.y * dis, a00.z * dis, a00.w * dis);
        o[1] = make_float4(a01.x * dis, a01.y * dis, a01.z * dis, a01.w * dis);
        o[2] = make_float4(a02.x * dis, a02.y * dis, a02.z * dis, a02.w * dis);
        o[3] = make_float4(a03.x * dis, a03.y * dis, a03.z * dis, a03.w * dis);
    }
    if (gr0 + 1 < N_NODES) {
        float dis = g_dis[gr0 + 1];
        float4* o = reinterpret_cast<float4*>(g_xw) + (size_t)(gr0 + 1) * 16 + cg * 4;
        o[0] = make_float4(a10.x * dis, a10.y * dis, a10.z * dis, a10.w * dis);
        o[1] = make_float4(a11.x * dis, a11.y * dis, a11.z * dis, a11.w * dis);
        o[2] = make_float4(a12.x * dis, a12.y * dis, a12.z * dis, a12.w * dis);
        o[3] = make_float4(a13.x * dis, a13.y * dis, a13.z * dis, a13.w * dis);
    }
}

// K4: bucket-fill CSR src lists; drains g_degi back to 0 (replay invariant).
__global__ void __launch_bounds__(256) k_fill(const int* __restrict__ ei) {
    int t = blockIdx.x * 256 + threadIdx.x;
    if (t < N_EDGES / 2) {
        int2 s = __ldg(reinterpret_cast<const int2*>(ei) + t);
        int2 d = __ldg(reinterpret_cast<const int2*>(ei + N_EDGES) + t);
        int p0 = g_off[d.x] + atomicAdd(&g_degi[d.x], -1) - 1;
        g_srcs[p0] = s.x;
        int p1 = g_off[d.y] + atomicAdd(&g_degi[d.y], -1) - 1;
        g_srcs[p1] = s.y;
    }
}

// K5: gather (R6-proven shape). One warp per node; lane owns 2 cols (float2).
// out[i] = dis[i] * (xs[i] + sum_j xs[src_j]) + b
__global__ void __launch_bounds__(256) k_gather(const float* __restrict__ b,
                                                float* __restrict__ out) {
    int warp = (blockIdx.x * 256 + threadIdx.x) >> 5;
    int lane = threadIdx.x & 31;
    if (warp >= N_NODES) return;
    const int i = warp;

    const float2* xs2 = reinterpret_cast<const float2*>(g_xw);
    const int col2 = i * (D / 2) + lane;

    float2 acc = __ldg(&xs2[col2]);                 // self term xs[i]
    int j   = __ldg(&g_off[i]);
    const int end = __ldg(&g_off[i + 1]);

    for (; j + 8 <= end; j += 8) {                  // MLP = 8
        int s0 = __ldg(&g_srcs[j + 0]);
        int s1 = __ldg(&g_srcs[j + 1]);
        int s2 = __ldg(&g_srcs[j + 2]);
        int s3 = __ldg(&g_srcs[j + 3]);
        int s4 = __ldg(&g_srcs[j + 4]);
        int s5 = __ldg(&g_srcs[j + 5]);
        int s6 = __ldg(&g_srcs[j + 6]);
        int s7 = __ldg(&g_srcs[j + 7]);
        float2 v0 = __ldg(&xs2[s0 * (D / 2) + lane]);
        float2 v1 = __ldg(&xs2[s1 * (D / 2) + lane]);
        float2 v2 = __ldg(&xs2[s2 * (D / 2) + lane]);
        float2 v3 = __ldg(&xs2[s3 * (D / 2) + lane]);
        float2 v4 = __ldg(&xs2[s4 * (D / 2) + lane]);
        float2 v5 = __ldg(&xs2[s5 * (D / 2) + lane]);
        float2 v6 = __ldg(&xs2[s6 * (D / 2) + lane]);
        float2 v7 = __ldg(&xs2[s7 * (D / 2) + lane]);
        acc.x += ((v0.x + v1.x) + (v2.x + v3.x)) + ((v4.x + v5.x) + (v6.x + v7.x));
        acc.y += ((v0.y + v1.y) + (v2.y + v3.y)) + ((v4.y + v5.y) + (v6.y + v7.y));
    }
    for (; j < end; j++) {
        int s = __ldg(&g_srcs[j]);
        float2 v = __ldg(&xs2[s * (D / 2) + lane]);
        acc.x += v.x;
        acc.y += v.y;
    }

    float dis = __ldg(&g_dis[i]);
    float2 bb = __ldg(reinterpret_cast<const float2*>(b) + lane);
    float2 o;
    o.x = acc.x * dis + bb.x;
    o.y = acc.y * dis + bb.y;
    reinterpret_cast<float2*>(out)[col2] = o;
}

extern "C" void kernel_launch(void* const* d_in, const int* in_sizes, int n_in,
                              void* d_out, int out_size) {
    const float* x  = (const float*)d_in[0];
    const int*   ei = (const int*)d_in[1];     // int64 in reference, delivered as int32
    const float* W  = (const float*)d_in[2];
    const float* b  = (const float*)d_in[3];
    float* out = (float*)d_out;

    (void)in_sizes; (void)n_in; (void)out_size;

    k_count <<<(N_EDGES / 4 + 255) / 256, 256>>>(ei);
    k_scan  <<<1, 1024>>>();
    k_gemm  <<<(N_NODES + 127) / 128, 256>>>(x, W);
    k_fill  <<<(N_EDGES / 2 + 255) / 256, 256>>>(ei);
    k_gather<<<(N_NODES * 32 + 255) / 256, 256>>>(b, out);
}

// round 12
// speedup vs baseline: 3.4863x; 2.0427x over previous
#include <cuda_runtime.h>
#include <cuda_fp16.h>

#define N_NODES 50000
#define N_EDGES 800000
#define D 64
#define SCAN_BLKS 196          // 196*256 = 50176 >= N_NODES

// Scratch (device globals: allocation-free; zero-initialized at module load).
// INVARIANT: g_degi is all-zero at entry of every kernel_launch call:
//   k_count builds it, k_fill drains it back to zero.
__device__ __half g_xh[N_NODES * D];     // xs = (x@W)*dis[row], fp16 (row = 128B)
__device__ float  g_dis[N_NODES];
__device__ int    g_degi[N_NODES];       // edge-only in-degree (drained by k_fill)
__device__ int    g_off[N_NODES + 1];    // CSR offsets (exclusive scan, +total)
__device__ int    g_srcs[N_EDGES];       // CSR src lists grouped by dst
__device__ int    g_part[SCAN_BLKS];     // per-block partial sums
__device__ int    g_pbase[SCAN_BLKS];    // exclusive base per block

// ---------------------------------------------------------------------------
// K1: count in-degrees. 4 edges per thread via int4.
__global__ void __launch_bounds__(256) k_count(const int* __restrict__ ei) {
    int t = blockIdx.x * 256 + threadIdx.x;
    if (t < N_EDGES / 4) {
        int4 d = __ldg(reinterpret_cast<const int4*>(ei + N_EDGES) + t);
        atomicAdd(&g_degi[d.x], 1);
        atomicAdd(&g_degi[d.y], 1);
        atomicAdd(&g_degi[d.z], 1);
        atomicAdd(&g_degi[d.w], 1);
    }
}

// K2a: per-block partial sums of g_degi (coalesced)
__global__ void __launch_bounds__(256) k_scanA() {
    int idx = blockIdx.x * 256 + threadIdx.x;
    int v = (idx < N_NODES) ? g_degi[idx] : 0;
    #pragma unroll
    for (int o = 16; o > 0; o >>= 1) v += __shfl_down_sync(~0u, v, o);
    __shared__ int ws[8];
    int lane = threadIdx.x & 31, wid = threadIdx.x >> 5;
    if (lane == 0) ws[wid] = v;
    __syncthreads();
    if (threadIdx.x == 0) {
        int s = 0;
        #pragma unroll
        for (int k = 0; k < 8; k++) s += ws[k];
        g_part[blockIdx.x] = s;
    }
}

// K2b: scan the SCAN_BLKS partials (1 block)
__global__ void __launch_bounds__(256) k_scanB() {
    __shared__ int sp[256];
    int t = threadIdx.x;
    int v = (t < SCAN_BLKS) ? g_part[t] : 0;
    sp[t] = v;
    __syncthreads();
    for (int o = 1; o < 256; o <<= 1) {
        int n = 0;
        if (t >= o) n = sp[t - o];
        __syncthreads();
        sp[t] += n;
        __syncthreads();
    }
    if (t < SCAN_BLKS) g_pbase[t] = sp[t] - v;      // exclusive
    if (t == 255) g_off[N_NODES] = sp[255];         // total = N_EDGES
}

// K2c: final offsets + dis = rsqrt(deg+1) (coalesced, block-local excl scan)
__global__ void __launch_bounds__(256) k_scanC() {
    int idx = blockIdx.x * 256 + threadIdx.x;
    int t = threadIdx.x, lane = t & 31, wid = t >> 5;
    int v = (idx < N_NODES) ? g_degi[idx] : 0;

    int inc = v;
    #pragma unroll
    for (int o = 1; o < 32; o <<= 1) {
        int n = __shfl_up_sync(~0u, inc, o);
        if (lane >= o) inc += n;
    }
    __shared__ int ws[8];
    if (lane == 31) ws[wid] = inc;
    __syncthreads();
    if (t == 0) {
        int run = 0;
        #pragma unroll
        for (int k = 0; k < 8; k++) { int tmp = ws[k]; ws[k] = run; run += tmp; }
    }
    __syncthreads();
    int excl = inc - v + ws[wid] + g_pbase[blockIdx.x];

    if (idx < N_NODES) {
        g_off[idx] = excl;
        g_dis[idx] = rsqrtf((float)(v + 1));        // +1 self loop
    }
}

// K3: xs = (x @ W) * dis[row], output fp16.
// 256 threads; tile = 128 rows. Thread = 2 rows x 16 cols.
#define XS 68                             // padded row stride (floats)
__global__ void __launch_bounds__(256) k_gemm(const float* __restrict__ x,
                                              const float* __restrict__ W) {
    __shared__ float sW[D * D];
    __shared__ float sx[128 * XS];
    float4* sW4 = reinterpret_cast<float4*>(sW);
    float4* sx4 = reinterpret_cast<float4*>(sx);

    const int tid = threadIdx.x;
    const int row0 = blockIdx.x * 128;

    #pragma unroll
    for (int i = tid; i < D * D / 4; i += 256)
        sW4[i] = reinterpret_cast<const float4*>(W)[i];
    #pragma unroll
    for (int i = tid; i < 128 * 16; i += 256) {
        int r = i >> 4;
        int c = i & 15;
        int gr = row0 + r;
        sx4[r * (XS / 4) + c] = (gr < N_NODES)
            ? __ldg(reinterpret_cast<const float4*>(x) + (size_t)gr * 16 + c)
            : make_float4(0.f, 0.f, 0.f, 0.f);
    }
    __syncthreads();

    const int r2 = tid >> 2;          // 0..63  -> rows 2*r2, 2*r2+1
    const int cg = tid & 3;           // 16-col group
    const float* x0 = sx + (2 * r2 + 0) * XS;
    const float* x1 = sx + (2 * r2 + 1) * XS;

    float4 a00, a01, a02, a03, a10, a11, a12, a13;
    a00 = a01 = a02 = a03 = make_float4(0.f, 0.f, 0.f, 0.f);
    a10 = a11 = a12 = a13 = a00;

    #pragma unroll 4
    for (int k = 0; k < D; k++) {
        float4 w0 = sW4[k * 16 + cg * 4 + 0];
        float4 w1 = sW4[k * 16 + cg * 4 + 1];
        float4 w2 = sW4[k * 16 + cg * 4 + 2];
        float4 w3 = sW4[k * 16 + cg * 4 + 3];
        float xa = x0[k];
        float xb = x1[k];
        a00.x += xa * w0.x; a00.y += xa * w0.y; a00.z += xa * w0.z; a00.w += xa * w0.w;
        a01.x += xa * w1.x; a01.y += xa * w1.y; a01.z += xa * w1.z; a01.w += xa * w1.w;
        a02.x += xa * w2.x; a02.y += xa * w2.y; a02.z += xa * w2.z; a02.w += xa * w2.w;
        a03.x += xa * w3.x; a03.y += xa * w3.y; a03.z += xa * w3.z; a03.w += xa * w3.w;
        a10.x += xb * w0.x; a10.y += xb * w0.y; a10.z += xb * w0.z; a10.w += xb * w0.w;
        a11.x += xb * w1.x; a11.y += xb * w1.y; a11.z += xb * w1.z; a11.w += xb * w1.w;
        a12.x += xb * w2.x; a12.y += xb * w2.y; a12.z += xb * w2.z; a12.w += xb * w2.w;
        a13.x += xb * w3.x; a13.y += xb * w3.y; a13.z += xb * w3.z; a13.w += xb * w3.w;
    }

    const int gr0 = row0 + 2 * r2;
    #pragma unroll
    for (int rr = 0; rr < 2; rr++) {
        int gr = gr0 + rr;
        if (gr >= N_NODES) break;
        float dis = g_dis[gr];
        float4 c0 = rr ? a10 : a00, c1 = rr ? a11 : a01;
        float4 c2 = rr ? a12 : a02, c3 = rr ? a13 : a03;
        __half2 h[8];
        h[0] = __floats2half2_rn(c0.x * dis, c0.y * dis);
        h[1] = __floats2half2_rn(c0.z * dis, c0.w * dis);
        h[2] = __floats2half2_rn(c1.x * dis, c1.y * dis);
        h[3] = __floats2half2_rn(c1.z * dis, c1.w * dis);
        h[4] = __floats2half2_rn(c2.x * dis, c2.y * dis);
        h[5] = __floats2half2_rn(c2.z * dis, c2.w * dis);
        h[6] = __floats2half2_rn(c3.x * dis, c3.y * dis);
        h[7] = __floats2half2_rn(c3.z * dis, c3.w * dis);
        uint4* dst = reinterpret_cast<uint4*>(g_xh + (size_t)gr * D) + cg * 2;
        dst[0] = *reinterpret_cast<uint4*>(&h[0]);
        dst[1] = *reinterpret_cast<uint4*>(&h[4]);
    }
}

// K4: bucket-fill CSR src lists; drains g_degi back to 0 (replay invariant).
// 4 edges per thread (4 independent atomics in flight).
__global__ void __launch_bounds__(256) k_fill(const int* __restrict__ ei) {
    int t = blockIdx.x * 256 + threadIdx.x;
    if (t < N_EDGES / 4) {
        int4 s = __ldg(reinterpret_cast<const int4*>(ei) + t);
        int4 d = __ldg(reinterpret_cast<const int4*>(ei + N_EDGES) + t);
        int o0 = g_off[d.x], o1 = g_off[d.y], o2 = g_off[d.z], o3 = g_off[d.w];
        int c0 = atomicAdd(&g_degi[d.x], -1);
        int c1 = atomicAdd(&g_degi[d.y], -1);
        int c2 = atomicAdd(&g_degi[d.z], -1);
        int c3 = atomicAdd(&g_degi[d.w], -1);
        g_srcs[o0 + c0 - 1] = s.x;
        g_srcs[o1 + c1 - 1] = s.y;
        g_srcs[o2 + c2 - 1] = s.z;
        g_srcs[o3 + c3 - 1] = s.w;
    }
}

// K5: gather. One warp per node (uniform control); lane owns one half2 (2 cols).
// One edge gather = 32 lanes x 4B = one 128B line.
// out[i] = dis[i] * (xs[i] + sum_j xs[src_j]) + b
__global__ void __launch_bounds__(256) k_gather(const float* __restrict__ b,
                                                float* __restrict__ out) {
    int warp = (blockIdx.x * 256 + threadIdx.x) >> 5;
    int lane = threadIdx.x & 31;
    if (warp >= N_NODES) return;
    const int i = warp;

    const __half2* xh = reinterpret_cast<const __half2*>(g_xh);
    const int col = i * 32 + lane;

    float2 acc = __half22float2(__ldg(&xh[col]));   // self term xs[i]
    int j = __ldg(&g_off[i]);
    const int end = __ldg(&g_off[i + 1]);

    for (; j + 8 <= end; j += 8) {                  // MLP = 8
        int s0 = __ldg(&g_srcs[j + 0]);
        int s1 = __ldg(&g_srcs[j + 1]);
        int s2 = __ldg(&g_srcs[j + 2]);
        int s3 = __ldg(&g_srcs[j + 3]);
        int s4 = __ldg(&g_srcs[j + 4]);
        int s5 = __ldg(&g_srcs[j + 5]);
        int s6 = __ldg(&g_srcs[j + 6]);
        int s7 = __ldg(&g_srcs[j + 7]);
        float2 v0 = __half22float2(__ldg(&xh[s0 * 32 + lane]));
        float2 v1 = __half22float2(__ldg(&xh[s1 * 32 + lane]));
        float2 v2 = __half22float2(__ldg(&xh[s2 * 32 + lane]));
        float2 v3 = __half22float2(__ldg(&xh[s3 * 32 + lane]));
        float2 v4 = __half22float2(__ldg(&xh[s4 * 32 + lane]));
        float2 v5 = __half22float2(__ldg(&xh[s5 * 32 + lane]));
        float2 v6 = __half22float2(__ldg(&xh[s6 * 32 + lane]));
        float2 v7 = __half22float2(__ldg(&xh[s7 * 32 + lane]));
        acc.x += ((v0.x + v1.x) + (v2.x + v3.x)) + ((v4.x + v5.x) + (v6.x + v7.x));
        acc.y += ((v0.y + v1.y) + (v2.y + v3.y)) + ((v4.y + v5.y) + (v6.y + v7.y));
    }
    for (; j < end; j++) {
        int s = __ldg(&g_srcs[j]);
        float2 v = __half22float2(__ldg(&xh[s * 32 + lane]));
        acc.x += v.x;
        acc.y += v.y;
    }

    float dis = __ldg(&g_dis[i]);
    float2 bb = __ldg(reinterpret_cast<const float2*>(b) + lane);
    float2 o;
    o.x = acc.x * dis + bb.x;
    o.y = acc.y * dis + bb.y;
    reinterpret_cast<float2*>(out)[col] = o;
}

extern "C" void kernel_launch(void* const* d_in, const int* in_sizes, int n_in,
                              void* d_out, int out_size) {
    const float* x  = (const float*)d_in[0];
    const int*   ei = (const int*)d_in[1];     // int64 in reference, delivered as int32
    const float* W  = (const float*)d_in[2];
    const float* b  = (const float*)d_in[3];
    float* out = (float*)d_out;

    (void)in_sizes; (void)n_in; (void)out_size;

    k_count <<<(N_EDGES / 4 + 255) / 256, 256>>>(ei);
    k_scanA <<<SCAN_BLKS, 256>>>();
    k_scanB <<<1, 256>>>();
    k_scanC <<<SCAN_BLKS, 256>>>();
    k_gemm  <<<(N_NODES + 127) / 128, 256>>>(x, W);
    k_fill  <<<(N_EDGES / 4 + 255) / 256, 256>>>(ei);
    k_gather<<<(N_NODES * 32 + 255) / 256, 256>>>(b, out);
}